// round 10
// baseline (speedup 1.0000x reference)
#include <cuda_runtime.h>

#define BB      8
#define NN      4096
#define CC      64
#define KD      32
#define KOUT    16
#define QT      256     // queries per CTA (2 per thread, f32x2 lanes)
#define CT      32      // candidates per chunk
#define NC      (NN / CT)
#define NTHREADS 128

// smem: qP2 16*128*4 u64 (64KB) | cB 2*32*64 f (16KB) | sqcb 2*32 f | topk 256*32 u64 (64KB)
#define SMEM_BYTES (65536 + 16384 + 256 + 65536)   // 147712

__device__ float g_sqc[BB * NN];

__device__ __forceinline__ void fma2(unsigned long long& d,
                                     unsigned long long a,
                                     unsigned long long b) {
    asm("fma.rn.f32x2 %0, %1, %2, %0;" : "+l"(d) : "l"(a), "l"(b));
}
__device__ __forceinline__ unsigned long long fma2g(unsigned long long a,
                                                    unsigned long long b,
                                                    unsigned long long c) {
    unsigned long long d;
    asm("fma.rn.f32x2 %0, %1, %2, %3;" : "=l"(d) : "l"(a), "l"(b), "l"(c));
    return d;
}
__device__ __forceinline__ unsigned long long add2(unsigned long long a,
                                                   unsigned long long b) {
    unsigned long long d;
    asm("add.rn.f32x2 %0, %1, %2;" : "=l"(d) : "l"(a), "l"(b));
    return d;
}
__device__ __forceinline__ unsigned long long pack2(float x) {
    unsigned long long r;
    asm("mov.b64 %0, {%1, %1};" : "=l"(r) : "f"(x));
    return r;
}
__device__ __forceinline__ void unpack2(float& lo, float& hi, unsigned long long v) {
    asm("mov.b64 {%0, %1}, %2;" : "=f"(lo), "=f"(hi) : "l"(v));
}
__device__ __forceinline__ unsigned int ord32(float f) {
    unsigned int b = __float_as_uint(f);
    return b ^ ((b & 0x80000000u) ? 0xFFFFFFFFu : 0x80000000u);
}
__device__ __forceinline__ float iord32(unsigned int y) {
    unsigned int b = (y & 0x80000000u) ? (y ^ 0x80000000u) : ~y;
    return __uint_as_float(b);
}
__device__ __forceinline__ void cpa16(void* smem_dst, const void* gsrc) {
    unsigned int s = (unsigned int)__cvta_generic_to_shared(smem_dst);
    asm volatile("cp.async.cg.shared.global [%0], [%1], 16;" :: "r"(s), "l"(gsrc));
}
#define CP_COMMIT() asm volatile("cp.async.commit_group;")
#define CP_WAIT0()  asm volatile("cp.async.wait_group 0;")

// ---- pre-kernel: exact XLA-order squared norms for all points ----
__global__ void __launch_bounds__(256) sqnorm_kernel(const float* __restrict__ pts) {
    int i = blockIdx.x * 256 + threadIdx.x;
    const float4* g4 = (const float4*)(pts + (size_t)i * CC);
    float a[32];
    #pragma unroll
    for (int t = 0; t < 16; ++t) {
        float4 v = g4[t];
        a[2 * t]     = __fadd_rn(__fmul_rn(v.x, v.x), __fmul_rn(v.y, v.y));
        a[2 * t + 1] = __fadd_rn(__fmul_rn(v.z, v.z), __fmul_rn(v.w, v.w));
    }
    #pragma unroll
    for (int off = 16; off >= 1; off >>= 1)
        #pragma unroll
        for (int l = 0; l < 16; ++l)
            if (l < off) a[l] = __fadd_rn(a[l], a[l + off]);
    g_sqc[i] = a[0];
}

__global__ void __launch_bounds__(NTHREADS, 1)
knn_pe_kernel(const float* __restrict__ xyz,
              const float* __restrict__ pts,
              float* __restrict__ out)
{
    extern __shared__ float smem[];
    unsigned long long* qP2 = (unsigned long long*)smem;  // [16 k4][128 p(^k4)][4 m] u64
    float* cB   = (float*)(qP2 + 16 * 128 * 4);           // [2 buf][32 c][64 k] swizzled
    float* sqcb = cB + 2 * CT * CC;                       // [2 buf][32]
    unsigned long long* topk = (unsigned long long*)(sqcb + 64);  // [256 q][32]

    const int tid   = threadIdx.x;
    const int b     = blockIdx.y;
    const int qbase = blockIdx.x * QT;
    const float* ptsB = pts + (size_t)b * NN * CC;
    const float* sqB  = g_sqc + b * NN;

    // ---- prologue: query tile -> paired k-major layout
    {
        const float4* g = (const float4*)(ptsB + (size_t)qbase * CC);
        #pragma unroll
        for (int it = 0; it < 32; ++it) {
            int f  = it * NTHREADS + tid;     // 0..4095
            int q  = f >> 4;                  // 0..255
            int k4 = f & 15;
            float4 v = g[f];
            int p = (q >> 1) ^ k4;            // store-side swizzle
            int l = q & 1;
            float* d = (float*)(qP2 + (((k4 << 7) + p) << 2));
            d[0 + l] = v.x; d[2 + l] = v.y; d[4 + l] = v.z; d[6 + l] = v.w;
        }
    }
    #pragma unroll
    for (int i = 0; i < 64; ++i)
        topk[i * NTHREADS + tid] = 0xFFFFFFFFFFFFFFFFull;

    const unsigned long long sqQp =
        *(const unsigned long long*)(sqB + qbase + 2 * tid);   // norms of q(2t), q(2t+1)

    // cp.async chunk 0 (+ its norms)
    #pragma unroll
    for (int it = 0; it < 4; ++it) {
        int f  = it * NTHREADS + tid;     // 0..511
        int c  = f >> 4;
        int k4 = f & 15;
        cpa16(cB + c * CC + ((k4 ^ (c & 15)) << 2),
              ptsB + (size_t)c * CC + (k4 << 2));
    }
    if (tid < 8) cpa16(sqcb + tid * 4, sqB + tid * 4);
    CP_COMMIT();

    const unsigned long long neg2 = pack2(-2.0f);
    float thr0 = iord32(0xFFFFFFFFu);     // NaN sentinels until rows fill
    float thr1 = iord32(0xFFFFFFFFu);
    unsigned long long* row0 = topk + (2 * tid) * KD;
    unsigned long long* row1 = row0 + KD;

    for (int chunk = 0; chunk < NC; ++chunk) {
        CP_WAIT0();
        __syncthreads();   // current buffers visible; prev GEMM reads done everywhere

        const float* cb  = cB + (chunk & 1) * (CT * CC);
        const float* sqc = sqcb + (chunk & 1) * CT;

        if (chunk + 1 < NC) {
            const float* src = ptsB + (size_t)(chunk + 1) * CT * CC;
            float* dst = cB + ((chunk + 1) & 1) * (CT * CC);
            #pragma unroll
            for (int it = 0; it < 4; ++it) {
                int f  = it * NTHREADS + tid;
                int c  = f >> 4;
                int k4 = f & 15;
                cpa16(dst + c * CC + ((k4 ^ (c & 15)) << 2),
                      src + (size_t)c * CC + (k4 << 2));
            }
            if (tid < 8)
                cpa16(sqcb + ((chunk + 1) & 1) * CT + tid * 4,
                      sqB + (chunk + 1) * CT + tid * 4);
        }
        CP_COMMIT();

        // ---- GEMM: 2 queries (f32x2 lanes) x 32 candidates, ascending-k chains
        unsigned long long acc[CT];
        #pragma unroll
        for (int c = 0; c < CT; ++c) acc[c] = 0ull;

        #pragma unroll 4
        for (int k4 = 0; k4 < 16; ++k4) {
            const unsigned long long* ap = qP2 + (((k4 << 7) + (tid ^ k4)) << 2);
            ulonglong2 a01 = *(const ulonglong2*)ap;        // k=+0, +1
            ulonglong2 a23 = *(const ulonglong2*)(ap + 2);  // k=+2, +3
            #pragma unroll
            for (int c = 0; c < CT; ++c) {
                float4 bv = *(const float4*)(cb + c * CC + ((k4 ^ (c & 15)) << 2));
                fma2(acc[c], a01.x, pack2(bv.x));
                fma2(acc[c], a01.y, pack2(bv.y));
                fma2(acc[c], a23.x, pack2(bv.z));
                fma2(acc[c], a23.y, pack2(bv.w));
            }
        }

        // ---- fused selection straight from registers
        const int cbase = chunk * CT;
        #pragma unroll 1
        for (int c8 = 0; c8 < CT; c8 += 8) {
            float a0[8], a1[8];
            #pragma unroll
            for (int u = 0; u < 8; ++u) {
                unsigned long long adj2 =
                    add2(fma2g(neg2, acc[c8 + u], sqQp), pack2(sqc[c8 + u]));
                unpack2(a0[u], a1[u], adj2);
            }
            float m0 = fminf(fminf(fminf(a0[0], a0[1]), fminf(a0[2], a0[3])),
                             fminf(fminf(a0[4], a0[5]), fminf(a0[6], a0[7])));
            if (!(m0 > thr0)) {
                #pragma unroll
                for (int u = 0; u < 8; ++u) {
                    if (a0[u] > thr0) continue;
                    unsigned long long key =
                        ((unsigned long long)ord32(a0[u]) << 32) |
                        (unsigned int)(cbase + c8 + u);
                    if (key < row0[KD - 1]) {
                        int p = KD - 1;
                        while (p > 0 && row0[p - 1] > key) { row0[p] = row0[p - 1]; --p; }
                        row0[p] = key;
                        thr0 = iord32((unsigned int)(row0[KD - 1] >> 32));
                    }
                }
            }
            float m1 = fminf(fminf(fminf(a1[0], a1[1]), fminf(a1[2], a1[3])),
                             fminf(fminf(a1[4], a1[5]), fminf(a1[6], a1[7])));
            if (!(m1 > thr1)) {
                #pragma unroll
                for (int u = 0; u < 8; ++u) {
                    if (a1[u] > thr1) continue;
                    unsigned long long key =
                        ((unsigned long long)ord32(a1[u]) << 32) |
                        (unsigned int)(cbase + c8 + u);
                    if (key < row1[KD - 1]) {
                        int p = KD - 1;
                        while (p > 0 && row1[p - 1] > key) { row1[p] = row1[p - 1]; --p; }
                        row1[p] = key;
                        thr1 = iord32((unsigned int)(row1[KD - 1] >> 32));
                    }
                }
            }
        }
    }

    // ---- epilogue: thread writes its own 2 queries (rows are thread-private)
    const float* xyzB = xyz + (size_t)b * NN * 3;
    #pragma unroll
    for (int l = 0; l < 2; ++l) {
        int q = 2 * tid + l;
        const unsigned long long* row = topk + q * KD;
        const float* xb = xyzB + (size_t)(qbase + q) * 3;
        float x0 = xb[0], x1 = xb[1], x2 = xb[2];
        float* o = out + (((size_t)b * NN + qbase + q) * KOUT) * 10;
        #pragma unroll 4
        for (int j = 0; j < KOUT; ++j) {
            unsigned int idx = (unsigned int)(row[2 * j] & 0xFFFFFFFFull);
            const float* nb = xyzB + (size_t)idx * 3;
            float n0 = nb[0], n1 = nb[1], n2 = nb[2];
            float r0 = x0 - n0, r1 = x1 - n1, r2 = x2 - n2;
            float d  = sqrtf(r0 * r0 + r1 * r1 + r2 * r2);
            float* oj = o + j * 10;
            oj[0] = d;
            oj[1] = r0; oj[2] = r1; oj[3] = r2;
            oj[4] = x0; oj[5] = x1; oj[6] = x2;
            oj[7] = n0; oj[8] = n1; oj[9] = n2;
        }
    }
}

extern "C" void kernel_launch(void* const* d_in, const int* in_sizes, int n_in,
                              void* d_out, int out_size) {
    const float* in0 = (const float*)d_in[0];
    const float* in1 = (const float*)d_in[1];
    const float* xyz;
    const float* pts;
    if (in_sizes[0] == BB * NN * 3) { xyz = in0; pts = in1; }
    else                            { xyz = in1; pts = in0; }

    cudaFuncSetAttribute(knn_pe_kernel,
                         cudaFuncAttributeMaxDynamicSharedMemorySize, SMEM_BYTES);

    sqnorm_kernel<<<BB * NN / 256, 256>>>(pts);
    dim3 grid(NN / QT, BB);
    knn_pe_kernel<<<grid, NTHREADS, SMEM_BYTES>>>(xyz, pts, (float*)d_out);
}

// round 11
// speedup vs baseline: 2.8833x; 2.8833x over previous
#include <cuda_runtime.h>

#define BB      8
#define NN      4096
#define CC      64
#define KD      32
#define KOUT    16
#define NTHREADS 256

#define K1_SMEM 65536   // qT 32KB + cT 32KB (reused as 64KB staging)

__device__ float g_sqc[BB * NN];
__device__ float g_adjT[(size_t)BB * NN * NN];   // [b][c][q], 512MB scratch

__device__ __forceinline__ void fma2(unsigned long long& d,
                                     unsigned long long a,
                                     unsigned long long b) {
    asm("fma.rn.f32x2 %0, %1, %2, %0;" : "+l"(d) : "l"(a), "l"(b));
}
__device__ __forceinline__ unsigned long long fma2g(unsigned long long a,
                                                    unsigned long long b,
                                                    unsigned long long c) {
    unsigned long long d;
    asm("fma.rn.f32x2 %0, %1, %2, %3;" : "=l"(d) : "l"(a), "l"(b), "l"(c));
    return d;
}
__device__ __forceinline__ unsigned long long add2(unsigned long long a,
                                                   unsigned long long b) {
    unsigned long long d;
    asm("add.rn.f32x2 %0, %1, %2;" : "=l"(d) : "l"(a), "l"(b));
    return d;
}
__device__ __forceinline__ unsigned long long pack2(float x) {
    unsigned long long r;
    asm("mov.b64 %0, {%1, %1};" : "=l"(r) : "f"(x));
    return r;
}
__device__ __forceinline__ unsigned int ord32(float f) {
    unsigned int b = __float_as_uint(f);
    return b ^ ((b & 0x80000000u) ? 0xFFFFFFFFu : 0x80000000u);
}
__device__ __forceinline__ float iord32(unsigned int y) {
    unsigned int b = (y & 0x80000000u) ? (y ^ 0x80000000u) : ~y;
    return __uint_as_float(b);
}

// ---- pre-kernel: exact XLA-order squared norms ----
__global__ void __launch_bounds__(256) sqnorm_kernel(const float* __restrict__ pts) {
    int i = blockIdx.x * 256 + threadIdx.x;
    const float4* g4 = (const float4*)(pts + (size_t)i * CC);
    float a[32];
    #pragma unroll
    for (int t = 0; t < 16; ++t) {
        float4 v = g4[t];
        a[2 * t]     = __fadd_rn(__fmul_rn(v.x, v.x), __fmul_rn(v.y, v.y));
        a[2 * t + 1] = __fadd_rn(__fmul_rn(v.z, v.z), __fmul_rn(v.w, v.w));
    }
    #pragma unroll
    for (int off = 16; off >= 1; off >>= 1)
        #pragma unroll
        for (int l = 0; l < 16; ++l)
            if (l < off) a[l] = __fadd_rn(a[l], a[l + off]);
    g_sqc[i] = a[0];
}

// ---- K1: adj GEMM, writes adjT[b][c][q] ----
__global__ void __launch_bounds__(NTHREADS, 2)
adj_gemm_kernel(const float* __restrict__ pts)
{
    extern __shared__ float smem[];
    float* qT = smem;            // [64 k][128 q]
    float* cT = smem + 8192;     // [128 c][64 k], f4-swizzled by k4 ^ (c>>3)
    float* stage = smem;         // epilogue: [128 c][128 q] f4-swizzled (reuses all 64KB)

    const int tid   = threadIdx.x;
    const int qtile = blockIdx.x;
    const int ctile = blockIdx.y;
    const int b     = blockIdx.z;
    const int qbase = qtile * 128;
    const int cbase = ctile * 128;
    const float* ptsB = pts + (size_t)b * NN * CC;

    // build qT (transposed) and cT (swizzled row-major)
    {
        const float4* gq = (const float4*)(ptsB + (size_t)qbase * CC);
        const float4* gc = (const float4*)(ptsB + (size_t)cbase * CC);
        #pragma unroll
        for (int it = 0; it < 8; ++it) {
            int f   = it * NTHREADS + tid;
            int row = f >> 4;
            int k4  = f & 15;
            float4 v = gq[f];
            qT[((k4 << 2) + 0) * 128 + row] = v.x;
            qT[((k4 << 2) + 1) * 128 + row] = v.y;
            qT[((k4 << 2) + 2) * 128 + row] = v.z;
            qT[((k4 << 2) + 3) * 128 + row] = v.w;
            float4 w = gc[f];
            *(float4*)(cT + row * 64 + ((k4 ^ ((row >> 3) & 15)) << 2)) = w;
        }
    }

    const int qg = tid >> 4;   // 0..15 : queries qg*8..+7
    const int cg = tid & 15;   // 0..15 : candidates cg*8..+7

    // norms
    unsigned long long sqQp[4];
    #pragma unroll
    for (int i = 0; i < 4; ++i)
        sqQp[i] = *(const unsigned long long*)(g_sqc + b * NN + qbase + (qg << 3) + 2 * i);
    float sc[8];
    {
        float4 s0 = *(const float4*)(g_sqc + b * NN + cbase + (cg << 3));
        float4 s1 = *(const float4*)(g_sqc + b * NN + cbase + (cg << 3) + 4);
        sc[0] = s0.x; sc[1] = s0.y; sc[2] = s0.z; sc[3] = s0.w;
        sc[4] = s1.x; sc[5] = s1.y; sc[6] = s1.z; sc[7] = s1.w;
    }
    __syncthreads();

    // ---- GEMM: inner[8q][8c], f32x2 query pairs, ascending-k chain
    unsigned long long acc[4][8];
    #pragma unroll
    for (int i = 0; i < 4; ++i)
        #pragma unroll
        for (int j = 0; j < 8; ++j) acc[i][j] = 0ull;

    #pragma unroll 2
    for (int k4 = 0; k4 < 16; ++k4) {
        float4 bv[8];
        #pragma unroll
        for (int j = 0; j < 8; ++j) {
            int c = (cg << 3) + j;
            bv[j] = *(const float4*)(cT + c * 64 + ((k4 ^ cg) << 2));
        }
        #pragma unroll
        for (int m = 0; m < 4; ++m) {
            int k = (k4 << 2) + m;
            const float* qrow = qT + k * 128 + (qg << 3);
            ulonglong2 a01 = *(const ulonglong2*)(qrow);
            ulonglong2 a23 = *(const ulonglong2*)(qrow + 4);
            unsigned long long bp[8];
            #pragma unroll
            for (int j = 0; j < 8; ++j) {
                float s = (m == 0) ? bv[j].x : (m == 1) ? bv[j].y
                        : (m == 2) ? bv[j].z : bv[j].w;
                bp[j] = pack2(s);
            }
            #pragma unroll
            for (int j = 0; j < 8; ++j) {
                fma2(acc[0][j], a01.x, bp[j]);
                fma2(acc[1][j], a01.y, bp[j]);
                fma2(acc[2][j], a23.x, bp[j]);
                fma2(acc[3][j], a23.y, bp[j]);
            }
        }
    }
    __syncthreads();   // all GEMM reads done; smem becomes staging

    // ---- epilogue: adj = (sqQ - 2*inner) + sqc, stage [c][q] f4-swizzled
    const unsigned long long neg2 = pack2(-2.0f);
    #pragma unroll
    for (int j = 0; j < 8; ++j) {
        int c = (cg << 3) + j;
        unsigned long long scp = pack2(sc[j]);
        #pragma unroll
        for (int i = 0; i < 4; ++i) {
            unsigned long long adj = add2(fma2g(neg2, acc[i][j], sqQp[i]), scp);
            int g = (qg << 1) + (i >> 1);          // logical q granule (q>>2)
            *(unsigned long long*)(stage + c * 128 + (((g ^ cg) << 2) | ((i & 1) << 1))) = adj;
        }
    }
    __syncthreads();

    // coalesced write to adjT[b][cbase+row][qbase + 4*c4]
    float* outB = g_adjT + ((size_t)b << 24);
    #pragma unroll
    for (int it = 0; it < 16; ++it) {
        int idx = it * NTHREADS + tid;   // 0..4095 float4s
        int row = idx >> 5;              // c within tile
        int c4  = idx & 31;              // logical q granule
        float4 v = *(const float4*)(stage + row * 128 + ((c4 ^ ((row >> 3) & 15)) << 2));
        *(float4*)(outB + ((size_t)(cbase + row) << 12) + qbase + (c4 << 2)) = v;
    }
}

// ---- K2: streaming top-k selection + gather/output ----
__global__ void __launch_bounds__(128)
select_kernel(const float* __restrict__ xyz, float* __restrict__ out)
{
    __shared__ unsigned long long topk[128 * KD];   // 32KB

    const int tid   = threadIdx.x;
    const int b     = blockIdx.y;
    const int qbase = blockIdx.x * 128;
    const int q     = qbase + tid;

    unsigned long long* row = topk + tid * KD;
    #pragma unroll
    for (int i = 0; i < KD; ++i) row[i] = 0xFFFFFFFFFFFFFFFFull;

    const float* col = g_adjT + ((size_t)b << 24) + q;   // stride 4096 per c
    float thr = iord32(0xFFFFFFFFu);   // NaN sentinel until row fills

    // depth-4 software pipeline, batches of 8 candidates
    float buf[4][8];
    #pragma unroll
    for (int pb = 0; pb < 3; ++pb)
        #pragma unroll
        for (int u = 0; u < 8; ++u)
            buf[pb][u] = col[(size_t)(pb * 8 + u) << 12];

    #pragma unroll 1
    for (int c8 = 0; c8 < NN; c8 += 8) {
        int stg = (c8 >> 3) & 3;
        if (c8 + 24 < NN) {
            int pre = (stg + 3) & 3;
            #pragma unroll
            for (int u = 0; u < 8; ++u)
                buf[pre][u] = col[(size_t)(c8 + 24 + u) << 12];
        }
        float av[8];
        #pragma unroll
        for (int u = 0; u < 8; ++u) av[u] = buf[stg][u];

        float mn = fminf(fminf(fminf(av[0], av[1]), fminf(av[2], av[3])),
                         fminf(fminf(av[4], av[5]), fminf(av[6], av[7])));
        if (mn > thr) continue;   // NaN thr -> enter until rows fill
        #pragma unroll
        for (int u = 0; u < 8; ++u) {
            if (av[u] > thr) continue;
            unsigned long long key =
                ((unsigned long long)ord32(av[u]) << 32) |
                (unsigned int)(c8 + u);
            if (key < row[KD - 1]) {
                int p = KD - 1;
                while (p > 0 && row[p - 1] > key) { row[p] = row[p - 1]; --p; }
                row[p] = key;
                thr = iord32((unsigned int)(row[KD - 1] >> 32));
            }
        }
    }

    // ---- gather epilogue (dilation 2: even ranks)
    const float* xyzB = xyz + (size_t)b * NN * 3;
    const float* xb = xyzB + (size_t)q * 3;
    float x0 = xb[0], x1 = xb[1], x2 = xb[2];
    float* o = out + (((size_t)b * NN + q) * KOUT) * 10;
    #pragma unroll 4
    for (int j = 0; j < KOUT; ++j) {
        unsigned int idx = (unsigned int)(row[2 * j] & 0xFFFFFFFFull);
        const float* nb = xyzB + (size_t)idx * 3;
        float n0 = nb[0], n1 = nb[1], n2 = nb[2];
        float r0 = x0 - n0, r1 = x1 - n1, r2 = x2 - n2;
        float d  = sqrtf(r0 * r0 + r1 * r1 + r2 * r2);
        float* oj = o + j * 10;
        oj[0] = d;
        oj[1] = r0; oj[2] = r1; oj[3] = r2;
        oj[4] = x0; oj[5] = x1; oj[6] = x2;
        oj[7] = n0; oj[8] = n1; oj[9] = n2;
    }
}

extern "C" void kernel_launch(void* const* d_in, const int* in_sizes, int n_in,
                              void* d_out, int out_size) {
    const float* in0 = (const float*)d_in[0];
    const float* in1 = (const float*)d_in[1];
    const float* xyz;
    const float* pts;
    if (in_sizes[0] == BB * NN * 3) { xyz = in0; pts = in1; }
    else                            { xyz = in1; pts = in0; }

    cudaFuncSetAttribute(adj_gemm_kernel,
                         cudaFuncAttributeMaxDynamicSharedMemorySize, K1_SMEM);

    sqnorm_kernel<<<BB * NN / 256, 256>>>(pts);

    dim3 g1(NN / 128, NN / 128, BB);   // x fastest: q-tiles share c-tile in L2
    adj_gemm_kernel<<<g1, NTHREADS, K1_SMEM>>>(pts);

    dim3 g2(NN / 128, BB);
    select_kernel<<<g2, 128>>>(xyz, (float*)d_out);
}